// round 16
// baseline (speedup 1.0000x reference)
#include <cuda_runtime.h>
#include <cuda_fp16.h>
#include <cstdint>

// Problem constants
#define T_STEPS 512
#define BATCH   64
#define HID     512
#define GATES   1536   // 3*HID
#define NLAYERS 2

// Scratch (device globals; no allocation)
__device__ float g_gates[(size_t)T_STEPS * BATCH * GATES];   // layer-1 input gates
__device__ uint32_t g_wfrag[(size_t)192 * 32 * 32 * 2];      // frag-ordered fp16 W_ih1
__device__ __half g_hmir1[2][BATCH][HID];                    // fp16 h1 mirror (dbl-buf)
__device__ __half g_hmir2[2][BATCH][HID];                    // fp16 h2 mirror (dbl-buf)

// Sync state
struct alignas(128) BarSt { unsigned arrive; unsigned gen; unsigned pad[30]; };
__device__ BarSt g_bars[4];                                  // end-of-kernel fence
struct alignas(128) Cnt { unsigned v; unsigned pad[31]; };
__device__ Cnt g_cntL[2][4][8];   // [layer][b-group][j-octile]; 32 arrivals/step

__device__ __forceinline__ uint32_t pack_h2(float a, float b) {
    __half2 h = __floats2half2_rn(a, b);
    return *(uint32_t*)&h;
}

#define MMA_F16(acc, a0, a1, a2, a3, b0, b1)                                   \
    asm volatile(                                                              \
        "mma.sync.aligned.m16n8k16.row.col.f32.f16.f16.f32 "                   \
        "{%0,%1,%2,%3}, {%4,%5,%6,%7}, {%8,%9}, {%0,%1,%2,%3};\n"              \
        : "+f"((acc)[0]), "+f"((acc)[1]), "+f"((acc)[2]), "+f"((acc)[3])       \
        : "r"(a0), "r"(a1), "r"(a2), "r"(a3), "r"(b0), "r"(b1))

__device__ __forceinline__ void cp_async16(uint32_t dst, const void* src) {
    asm volatile("cp.async.cg.shared.global [%0], [%1], 16;" :: "r"(dst), "l"(src));
}
__device__ __forceinline__ unsigned ld_acq_gpu(unsigned* p) {
    unsigned v;
    asm volatile("ld.acquire.gpu.global.u32 %0, [%1];" : "=r"(v) : "l"(p) : "memory");
    return v;
}
__device__ __forceinline__ void red_add_rel_gpu(unsigned* p) {
    asm volatile("red.release.gpu.global.add.u32 [%0], 1;" :: "l"(p) : "memory");
}
__device__ __forceinline__ unsigned atom_add_rel_gpu(unsigned* p) {
    unsigned old;
    asm volatile("atom.add.release.gpu.global.u32 %0, [%1], 1;"
                 : "=r"(old) : "l"(p) : "memory");
    return old;
}

// ---------------------------------------------------------------------------
// Pre-convert W (1536 x 512 fp32) into fp16 MMA B-fragment order (layer 1).
// ---------------------------------------------------------------------------
__global__ __launch_bounds__(256) void conv_wfrag_h(
    const float* __restrict__ W, uint32_t* __restrict__ F)
{
    int idx = blockIdx.x * 256 + threadIdx.x;
    int r    = idx & 1;
    int lane = (idx >> 1) & 31;
    int k16  = (idx >> 6) & 31;
    int nt   = idx >> 11;
    int n = nt * 8 + (lane >> 2);
    int k = k16 * 16 + (lane & 3) * 2 + r * 8;
    const float* p = W + (size_t)n * HID + k;
    F[idx] = pack_h2(p[0], p[1]);
}

// ---------------------------------------------------------------------------
// fp16 GEMM for layer-1 input projection.
// ---------------------------------------------------------------------------
#define APH 20

__global__ __launch_bounds__(256) void gemm_f16(
    const float* __restrict__ A, const uint32_t* __restrict__ Wf,
    const float* __restrict__ bias, float* __restrict__ C,
    int M, int N, int K)
{
    __shared__ uint32_t As[2][64][APH];

    const int bm  = blockIdx.y * 64;
    const int bnt = blockIdx.x * 16;
    const int tid = threadIdx.x;
    const int wid = tid >> 5;
    const int lane = tid & 31;
    const int wm = wid & 1;
    const int wn = wid >> 1;
    const int frow = lane >> 2;
    const int fk = lane & 3;

    float acc[2][4][4];
#pragma unroll
    for (int i = 0; i < 2; i++)
#pragma unroll
        for (int j = 0; j < 4; j++)
#pragma unroll
            for (int e = 0; e < 4; e++) acc[i][j][e] = 0.0f;

    const int lm = tid >> 2;
    const int lq = tid & 3;

    float4 pre[2];
    auto ldA = [&](int k0) {
#pragma unroll
        for (int it = 0; it < 2; it++) {
            int kq = lq * 2 + it;
            pre[it] = *(const float4*)(A + (size_t)(bm + lm) * K + k0 + kq * 4);
        }
    };
    auto stA = [&](int buf) {
#pragma unroll
        for (int it = 0; it < 2; it++) {
            int kq = lq * 2 + it;
            uint2 u = make_uint2(pack_h2(pre[it].x, pre[it].y),
                                 pack_h2(pre[it].z, pre[it].w));
            *(uint2*)&As[buf][lm][kq * 2] = u;
        }
    };

    ldA(0);
    stA(0);
    int buf = 0;

    for (int k0 = 0; k0 < K; k0 += 32) {
        __syncthreads();
        bool next = (k0 + 32 < K);
        if (next) ldA(k0 + 32);

#pragma unroll
        for (int sub = 0; sub < 2; sub++) {
            const int k16g = (k0 >> 4) + sub;
            uint32_t b0[4], b1[4];
#pragma unroll
            for (int j = 0; j < 4; j++) {
                size_t nt = (size_t)(bnt + wn * 4 + j);
                const uint2 v = __ldg((const uint2*)(Wf + ((nt * 32 + k16g) * 32 + lane) * 2));
                b0[j] = v.x; b1[j] = v.y;
            }
            uint32_t a[2][4];
#pragma unroll
            for (int i = 0; i < 2; i++) {
                int r0 = wm * 32 + i * 16 + frow;
                a[i][0] = As[buf][r0][sub * 8 + fk];
                a[i][1] = As[buf][r0 + 8][sub * 8 + fk];
                a[i][2] = As[buf][r0][sub * 8 + 4 + fk];
                a[i][3] = As[buf][r0 + 8][sub * 8 + 4 + fk];
            }
#pragma unroll
            for (int i = 0; i < 2; i++)
#pragma unroll
                for (int j = 0; j < 4; j++)
                    MMA_F16(acc[i][j], a[i][0], a[i][1], a[i][2], a[i][3],
                            b0[j], b1[j]);
        }
        if (next) stA(buf ^ 1);
        buf ^= 1;
    }

#pragma unroll
    for (int i = 0; i < 2; i++) {
        int mrow = bm + wm * 32 + i * 16 + frow;
#pragma unroll
        for (int j = 0; j < 4; j++) {
            int ncol = (bnt + wn * 4 + j) * 8 + fk * 2;
            float c0 = bias[ncol], c1 = bias[ncol + 1];
            *(float2*)(C + (size_t)mrow * N + ncol) =
                make_float2(acc[i][j][0] + c0, acc[i][j][1] + c1);
            *(float2*)(C + (size_t)(mrow + 8) * N + ncol) =
                make_float2(acc[i][j][2] + c0, acc[i][j][3] + c1);
        }
    }
}

// ---------------------------------------------------------------------------
// Gen-based barrier (used once at kernel end for counter reset)
// ---------------------------------------------------------------------------
__device__ __forceinline__ void group_barrier(int grp, unsigned nb)
{
    __syncthreads();
    if (threadIdx.x == 0) {
        unsigned gen0 = *(volatile unsigned*)&g_bars[grp].gen;
        unsigned prev = atom_add_rel_gpu(&g_bars[grp].arrive);
        if (prev == nb - 1) {
            *(volatile unsigned*)&g_bars[grp].arrive = 0;
            atom_add_rel_gpu(&g_bars[grp].gen);
        } else {
            while (ld_acq_gpu(&g_bars[grp].gen) == gen0) { }
        }
    }
    __syncthreads();
}

// ---------------------------------------------------------------------------
// Fused 2-layer persistent kernel, SINGLE MMA/reduce round per iteration:
// iteration t stages h1[t-1] + h2[t-2], runs l1-rec / l2-inp / l2-rec MMAs
// together (l1-rec & l2-inp share A fragments), one syncthreads, then both
// gatings with per-warp releases (32 arrivals per octile per step).
// 128 CTAs = 32 j-tiles x 4 b-groups, 256 threads.
// ---------------------------------------------------------------------------
#define HSH_PITCH 520
#define PS_PITCH 50
#define W2_ENTRIES (6 * 32 * 32)
#define PS_BYTES (8 * 16 * PS_PITCH * 4)
#define SM_W2I 0
#define SM_W2H (W2_ENTRIES * 8)
#define SM_PSA (2 * W2_ENTRIES * 8)
#define SM_PSB (SM_PSA + PS_BYTES)
#define SM_PSC (SM_PSB + PS_BYTES)
#define SM_H1  (SM_PSC + PS_BYTES)
#define SM_H2  (SM_H1 + 16 * HSH_PITCH * 2)
#define FUSED_SMEM_BYTES (SM_H2 + 16 * HSH_PITCH * 2)   // 208384 B

__global__ __launch_bounds__(256, 1) void gru_fused2(
    const float* __restrict__ gx1_all,  // (T, B, 3H) layer-1 input gates
    const float* __restrict__ h0,       // (L, B, H)
    const float* __restrict__ Whh1,     // (3H, H)
    const float* __restrict__ bhh1,     // (3H)
    const float* __restrict__ Wih2,     // (3H, H)
    const float* __restrict__ bih2,     // (3H)
    const float* __restrict__ Whh2,     // (3H, H)
    const float* __restrict__ bhh2,     // (3H)
    float* __restrict__ out)            // (T, B, H) layer-2 output
{
    extern __shared__ char smc[];
    uint2*  W2i  = (uint2*)(smc + SM_W2I);
    uint2*  W2h  = (uint2*)(smc + SM_W2H);
    float*  Ps_a = (float*)(smc + SM_PSA);
    float*  Ps_b = (float*)(smc + SM_PSB);
    float*  Ps_c = (float*)(smc + SM_PSC);
    __half* h1_s = (__half*)(smc + SM_H1);
    __half* h2_s = (__half*)(smc + SM_H2);

    const int jt = blockIdx.x & 31;
    const int bt = blockIdx.x >> 5;
    const int j0 = jt * 16;
    const int b0 = bt * 16;
    const int tid = threadIdx.x;
    const int w = tid >> 5;
    const int lane = tid & 31;
    const int my_oct = jt >> 2;

    const float* h0_l1 = h0;
    const float* h0_l2 = h0 + (size_t)BATCH * HID;

    // ---- one-time: W_hh1 frags -> registers; W_ih2/W_hh2 frags -> SMEM
    uint32_t wb0[6][4], wb1[6][4];
    {
        const int colq = lane >> 2;
        const int kq2 = (lane & 3) * 2;
#pragma unroll
        for (int tl = 0; tl < 6; tl++) {
            int g = tl >> 1;
            int col = j0 + (tl & 1) * 8 + colq;
            const float* wrow = Whh1 + (size_t)(g * HID + col) * HID;
#pragma unroll
            for (int kk = 0; kk < 4; kk++) {
                int ks = (w * 4 + kk) * 16 + kq2;
                wb0[tl][kk] = pack_h2(wrow[ks], wrow[ks + 1]);
                wb1[tl][kk] = pack_h2(wrow[ks + 8], wrow[ks + 9]);
            }
        }
    }
    for (int i = tid; i < W2_ENTRIES; i += 256) {
        int lane_ = i & 31;
        int k16_ = (i >> 5) & 31;
        int tl_ = i >> 10;
        int g = tl_ >> 1;
        int col = j0 + (tl_ & 1) * 8 + (lane_ >> 2);
        int k = k16_ * 16 + (lane_ & 3) * 2;
        const float* wi = Wih2 + (size_t)(g * HID + col) * HID;
        const float* wh = Whh2 + (size_t)(g * HID + col) * HID;
        W2i[i] = make_uint2(pack_h2(wi[k], wi[k + 1]), pack_h2(wi[k + 8], wi[k + 9]));
        W2h[i] = make_uint2(pack_h2(wh[k], wh[k + 1]), pack_h2(wh[k + 8], wh[k + 9]));
    }

    const int gb = tid >> 4;
    const int gj = tid & 15;
    const int bg_g = b0 + gb;
    const int jg_g = j0 + gj;
    const float b1r = bhh1[jg_g];
    const float b1z = bhh1[HID + jg_g];
    const float b1n = bhh1[2 * HID + jg_g];
    const float i2r = bih2[jg_g];
    const float i2z = bih2[HID + jg_g];
    const float i2n = bih2[2 * HID + jg_g];
    const float h2r = bhh2[jg_g];
    const float h2z = bhh2[HID + jg_g];
    const float h2n = bhh2[2 * HID + jg_g];

    const int frow = lane >> 2;
    const int fk = lane & 3;
    const int pm = lane >> 2;
    const int pnc = 2 * (lane & 3);

    float hpv1 = __ldg(h0_l1 + (size_t)bg_g * HID + jg_g);
    float hpv2 = __ldg(h0_l2 + (size_t)bg_g * HID + jg_g);

    const float* gxp = gx1_all + (size_t)bg_g * GATES;
    float xr = __ldg(gxp + jg_g);
    float xz = __ldg(gxp + HID + jg_g);
    float xn = __ldg(gxp + 2 * HID + jg_g);

    __syncthreads();   // W2 SMEM ready

    for (int t = 0; t <= T_STEPS; t++) {
        const int s = t - 1;
        const bool do_l1 = (t < T_STEPS);
        const bool do_l2 = (t >= 1);

        // ===== stage h1[t-1] (always needed: l1-rec at t<512, l2-inp at t>=1)
        if (t == 0) {
#pragma unroll
            for (int it = 0; it < 8; it++) {
                int f = it * 32 + lane;
                int rr = f >> 4;
                int c4 = f & 15;
                float4 v = *((const float4*)(h0_l1 + (size_t)(b0 + rr) * HID + w * 64) + c4);
                uint2 u = make_uint2(pack_h2(v.x, v.y), pack_h2(v.z, v.w));
                *(uint2*)&h1_s[rr * HSH_PITCH + w * 64 + c4 * 4] = u;
            }
        } else {
            unsigned target = 32u * (unsigned)t;
            unsigned* cp = &g_cntL[0][bt][w].v;
            while (ld_acq_gpu(cp) < target) { }
            const __half* mir = &g_hmir1[(t - 1) & 1][b0][0];
#pragma unroll
            for (int it = 0; it < 4; it++) {
                int f = it * 32 + lane;
                int rr = f >> 3;
                int c  = f & 7;
                uint32_t dst = (uint32_t)__cvta_generic_to_shared(
                    &h1_s[rr * HSH_PITCH + w * 64 + c * 8]);
                cp_async16(dst, mir + (size_t)rr * HID + w * 64 + c * 8);
            }
            asm volatile("cp.async.commit_group;");
        }

        // ===== stage h2[s-1]
        if (do_l2) {
            if (s == 0) {
#pragma unroll
                for (int it = 0; it < 8; it++) {
                    int f = it * 32 + lane;
                    int rr = f >> 4;
                    int c4 = f & 15;
                    float4 v = *((const float4*)(h0_l2 + (size_t)(b0 + rr) * HID + w * 64) + c4);
                    uint2 u = make_uint2(pack_h2(v.x, v.y), pack_h2(v.z, v.w));
                    *(uint2*)&h2_s[rr * HSH_PITCH + w * 64 + c4 * 4] = u;
                }
            } else {
                unsigned target = 32u * (unsigned)s;
                unsigned* cp = &g_cntL[1][bt][w].v;
                while (ld_acq_gpu(cp) < target) { }
                const __half* mir = &g_hmir2[(s - 1) & 1][b0][0];
#pragma unroll
                for (int it = 0; it < 4; it++) {
                    int f = it * 32 + lane;
                    int rr = f >> 3;
                    int c  = f & 7;
                    uint32_t dst = (uint32_t)__cvta_generic_to_shared(
                        &h2_s[rr * HSH_PITCH + w * 64 + c * 8]);
                    cp_async16(dst, mir + (size_t)rr * HID + w * 64 + c * 8);
                }
                asm volatile("cp.async.commit_group;");
            }
        }
        asm volatile("cp.async.wait_all;");
        __syncwarp();

        // ===== all three GEMM slices (warp's own k-slice only)
        {
            float accA[6][4], accC[6][4];
#pragma unroll
            for (int tl = 0; tl < 6; tl++) {
                accA[tl][0] = 0.f; accA[tl][1] = 0.f; accA[tl][2] = 0.f; accA[tl][3] = 0.f;
                accC[tl][0] = 0.f; accC[tl][1] = 0.f; accC[tl][2] = 0.f; accC[tl][3] = 0.f;
            }
#pragma unroll
            for (int kk = 0; kk < 4; kk++) {
                int k16g = w * 4 + kk;
                int kbase = k16g * 16;
                uint32_t a0 = *(const uint32_t*)&h1_s[frow * HSH_PITCH + kbase + fk * 2];
                uint32_t a1 = *(const uint32_t*)&h1_s[(frow + 8) * HSH_PITCH + kbase + fk * 2];
                uint32_t a2 = *(const uint32_t*)&h1_s[frow * HSH_PITCH + kbase + 8 + fk * 2];
                uint32_t a3 = *(const uint32_t*)&h1_s[(frow + 8) * HSH_PITCH + kbase + 8 + fk * 2];
                if (do_l1) {
#pragma unroll
                    for (int tl = 0; tl < 6; tl++)
                        MMA_F16(accA[tl], a0, a1, a2, a3, wb0[tl][kk], wb1[tl][kk]);
                }
                if (do_l2) {
#pragma unroll
                    for (int tl = 0; tl < 6; tl++) {
                        uint2 bv = W2i[(tl * 32 + k16g) * 32 + lane];
                        MMA_F16(accC[tl], a0, a1, a2, a3, bv.x, bv.y);
                    }
                }
            }
            if (do_l1) {
#pragma unroll
                for (int tl = 0; tl < 6; tl++) {
                    *(float2*)&Ps_a[(w * 16 + pm) * PS_PITCH + tl * 8 + pnc] =
                        make_float2(accA[tl][0], accA[tl][1]);
                    *(float2*)&Ps_a[(w * 16 + pm + 8) * PS_PITCH + tl * 8 + pnc] =
                        make_float2(accA[tl][2], accA[tl][3]);
                }
            }
            if (do_l2) {
#pragma unroll
                for (int tl = 0; tl < 6; tl++) {
                    *(float2*)&Ps_c[(w * 16 + pm) * PS_PITCH + tl * 8 + pnc] =
                        make_float2(accC[tl][0], accC[tl][1]);
                    *(float2*)&Ps_c[(w * 16 + pm + 8) * PS_PITCH + tl * 8 + pnc] =
                        make_float2(accC[tl][2], accC[tl][3]);
                }
                // l2 recurrent
                float accB[6][4];
#pragma unroll
                for (int tl = 0; tl < 6; tl++) {
                    accB[tl][0] = 0.f; accB[tl][1] = 0.f; accB[tl][2] = 0.f; accB[tl][3] = 0.f;
                }
#pragma unroll
                for (int kk = 0; kk < 4; kk++) {
                    int k16g = w * 4 + kk;
                    int kbase = k16g * 16;
                    uint32_t a0 = *(const uint32_t*)&h2_s[frow * HSH_PITCH + kbase + fk * 2];
                    uint32_t a1 = *(const uint32_t*)&h2_s[(frow + 8) * HSH_PITCH + kbase + fk * 2];
                    uint32_t a2 = *(const uint32_t*)&h2_s[frow * HSH_PITCH + kbase + 8 + fk * 2];
                    uint32_t a3 = *(const uint32_t*)&h2_s[(frow + 8) * HSH_PITCH + kbase + 8 + fk * 2];
#pragma unroll
                    for (int tl = 0; tl < 6; tl++) {
                        uint2 bv = W2h[(tl * 32 + k16g) * 32 + lane];
                        MMA_F16(accB[tl], a0, a1, a2, a3, bv.x, bv.y);
                    }
                }
#pragma unroll
                for (int tl = 0; tl < 6; tl++) {
                    *(float2*)&Ps_b[(w * 16 + pm) * PS_PITCH + tl * 8 + pnc] =
                        make_float2(accB[tl][0], accB[tl][1]);
                    *(float2*)&Ps_b[(w * 16 + pm + 8) * PS_PITCH + tl * 8 + pnc] =
                        make_float2(accB[tl][2], accB[tl][3]);
                }
            }
        }

        __syncthreads();   // sync1: all partials visible

        // ===== layer-1 reduce + gating + per-warp release
        if (do_l1) {
            float hr = 0.f, hz = 0.f, hn = 0.f;
#pragma unroll
            for (int ww = 0; ww < 8; ww++) {
                const float* p = &Ps_a[(ww * 16 + gb) * PS_PITCH];
                hr += p[gj];
                hz += p[16 + gj];
                hn += p[32 + gj];
            }
            float r = 1.0f / (1.0f + __expf(-(xr + hr + b1r)));
            float z = 1.0f / (1.0f + __expf(-(xz + hz + b1z)));
            float n = tanhf(xn + r * (hn + b1n));
            float h1new = (1.0f - z) * n + z * hpv1;
            hpv1 = h1new;

            g_hmir1[t & 1][bg_g][jg_g] = __float2half_rn(h1new);
            __syncwarp();
            if (lane == 0)
                red_add_rel_gpu(&g_cntL[0][bt][my_oct].v);
        }

        // ===== layer-2 reduce + gating + per-warp release
        if (do_l2) {
            float xr2 = 0.f, xz2 = 0.f, xn2 = 0.f;
            float hr2 = 0.f, hz2 = 0.f, hn2 = 0.f;
#pragma unroll
            for (int ww = 0; ww < 8; ww++) {
                const float* pa = &Ps_c[(ww * 16 + gb) * PS_PITCH];
                const float* pb = &Ps_b[(ww * 16 + gb) * PS_PITCH];
                xr2 += pa[gj];  xz2 += pa[16 + gj];  xn2 += pa[32 + gj];
                hr2 += pb[gj];  hz2 += pb[16 + gj];  hn2 += pb[32 + gj];
            }
            float r2 = 1.0f / (1.0f + __expf(-(xr2 + i2r + hr2 + h2r)));
            float z2 = 1.0f / (1.0f + __expf(-(xz2 + i2z + hz2 + h2z)));
            float n2 = tanhf(xn2 + i2n + r2 * (hn2 + h2n));
            float h2new = (1.0f - z2) * n2 + z2 * hpv2;
            hpv2 = h2new;

            g_hmir2[s & 1][bg_g][jg_g] = __float2half_rn(h2new);
            out[(size_t)s * BATCH * HID + (size_t)bg_g * HID + jg_g] = h2new;
            __syncwarp();
            if (lane == 0 && s != T_STEPS - 1)
                red_add_rel_gpu(&g_cntL[1][bt][my_oct].v);
        }

        // prefetch next gx1 (off critical path)
        if (do_l1) {
            int tn = (t + 1 < T_STEPS) ? t + 1 : t;
            const float* gxn = gx1_all + (size_t)tn * BATCH * GATES + (size_t)bg_g * GATES;
            xr = __ldg(gxn + jg_g);
            xz = __ldg(gxn + HID + jg_g);
            xn = __ldg(gxn + 2 * HID + jg_g);
        }

        __syncthreads();   // sync2: protect Ps reuse next iteration
    }

    // end: fence the group, then reset this group's counters (both layers)
    group_barrier(bt, 32);
    if (jt == 0 && tid < 8) {
        *(volatile unsigned*)&g_cntL[0][bt][tid].v = 0;
        *(volatile unsigned*)&g_cntL[1][bt][tid].v = 0;
    }
}

// ---------------------------------------------------------------------------
extern "C" void kernel_launch(void* const* d_in, const int* in_sizes, int n_in,
                              void* d_out, int out_size)
{
    const float* x    = (const float*)d_in[0];
    const float* h0   = (const float*)d_in[1];
    const float* w_ih = (const float*)d_in[2];
    const float* w_hh = (const float*)d_in[3];
    const float* b_ih = (const float*)d_in[4];
    const float* b_hh = (const float*)d_in[5];
    float* out_final  = (float*)d_out;

    float* gates; uint32_t* wfrag;
    cudaGetSymbolAddress((void**)&gates, g_gates);
    cudaGetSymbolAddress((void**)&wfrag, g_wfrag);

    static int smem_configured = 0;
    if (!smem_configured) {
        cudaFuncSetAttribute(gru_fused2,
                             cudaFuncAttributeMaxDynamicSharedMemorySize, FUSED_SMEM_BYTES);
        smem_configured = 1;
    }

    const int M = T_STEPS * BATCH;
    const int K = HID;

    // layer-1 input GEMM (parallel, off the serial path)
    conv_wfrag_h<<<1536, 256>>>(w_ih, wfrag);
    dim3 ggrid(GATES / 128, M / 64);
    gemm_f16<<<ggrid, 256>>>(x, wfrag, b_ih, gates, M, GATES, K);

    // fused 2-layer pipelined recurrence (single MMA/reduce round per iter)
    gru_fused2<<<128, 256, FUSED_SMEM_BYTES>>>(
        gates, h0,
        w_hh, b_hh,                                   // layer-1 recurrent
        w_ih + (size_t)GATES * HID, b_ih + GATES,     // layer-2 input
        w_hh + (size_t)GATES * HID, b_hh + GATES,     // layer-2 recurrent
        out_final);
}

// round 17
// speedup vs baseline: 1.4780x; 1.4780x over previous
#include <cuda_runtime.h>
#include <cuda_fp16.h>
#include <cstdint>

// Problem constants
#define T_STEPS 512
#define BATCH   64
#define HID     512
#define GATES   1536   // 3*HID
#define NLAYERS 2

// Scratch (device globals; no allocation)
__device__ float g_gates[(size_t)T_STEPS * BATCH * GATES];   // layer-1 input gates
__device__ uint32_t g_wfrag[(size_t)192 * 32 * 32 * 2];      // frag-ordered fp16 W_ih1
__device__ __half g_hmir1[2][BATCH][HID];                    // fp16 h1 mirror (dbl-buf)
__device__ __half g_hmir2[2][BATCH][HID];                    // fp16 h2 mirror (dbl-buf)

// Sync state
struct alignas(128) BarSt { unsigned arrive; unsigned gen; unsigned pad[30]; };
__device__ BarSt g_bars[4];                                  // end-of-kernel fence
struct alignas(128) Cnt { unsigned v; unsigned pad[31]; };
__device__ Cnt g_cntL[2][4][8];   // [layer][b-group][j-octile]; +4 per step

__device__ __forceinline__ uint32_t pack_h2(float a, float b) {
    __half2 h = __floats2half2_rn(a, b);
    return *(uint32_t*)&h;
}

#define MMA_F16(acc, a0, a1, a2, a3, b0, b1)                                   \
    asm volatile(                                                              \
        "mma.sync.aligned.m16n8k16.row.col.f32.f16.f16.f32 "                   \
        "{%0,%1,%2,%3}, {%4,%5,%6,%7}, {%8,%9}, {%0,%1,%2,%3};\n"              \
        : "+f"((acc)[0]), "+f"((acc)[1]), "+f"((acc)[2]), "+f"((acc)[3])       \
        : "r"(a0), "r"(a1), "r"(a2), "r"(a3), "r"(b0), "r"(b1))

__device__ __forceinline__ void cp_async16(uint32_t dst, const void* src) {
    asm volatile("cp.async.cg.shared.global [%0], [%1], 16;" :: "r"(dst), "l"(src));
}
__device__ __forceinline__ unsigned ld_acq_gpu(unsigned* p) {
    unsigned v;
    asm volatile("ld.acquire.gpu.global.u32 %0, [%1];" : "=r"(v) : "l"(p) : "memory");
    return v;
}
__device__ __forceinline__ void red_add_rel_gpu(unsigned* p) {
    asm volatile("red.release.gpu.global.add.u32 [%0], 1;" :: "l"(p) : "memory");
}
__device__ __forceinline__ unsigned atom_add_rel_gpu(unsigned* p) {
    unsigned old;
    asm volatile("atom.add.release.gpu.global.u32 %0, [%1], 1;"
                 : "=r"(old) : "l"(p) : "memory");
    return old;
}
#define BARX(id) asm volatile("bar.sync %0, 128;" :: "r"(id) : "memory")

// ---------------------------------------------------------------------------
// Pre-convert W (1536 x 512 fp32) into fp16 MMA B-fragment order (layer 1).
// ---------------------------------------------------------------------------
__global__ __launch_bounds__(256) void conv_wfrag_h(
    const float* __restrict__ W, uint32_t* __restrict__ F)
{
    int idx = blockIdx.x * 256 + threadIdx.x;
    int r    = idx & 1;
    int lane = (idx >> 1) & 31;
    int k16  = (idx >> 6) & 31;
    int nt   = idx >> 11;
    int n = nt * 8 + (lane >> 2);
    int k = k16 * 16 + (lane & 3) * 2 + r * 8;
    const float* p = W + (size_t)n * HID + k;
    F[idx] = pack_h2(p[0], p[1]);
}

// ---------------------------------------------------------------------------
// fp16 GEMM for layer-1 input projection.
// ---------------------------------------------------------------------------
#define APH 20

__global__ __launch_bounds__(256) void gemm_f16(
    const float* __restrict__ A, const uint32_t* __restrict__ Wf,
    const float* __restrict__ bias, float* __restrict__ C,
    int M, int N, int K)
{
    __shared__ uint32_t As[2][64][APH];

    const int bm  = blockIdx.y * 64;
    const int bnt = blockIdx.x * 16;
    const int tid = threadIdx.x;
    const int wid = tid >> 5;
    const int lane = tid & 31;
    const int wm = wid & 1;
    const int wn = wid >> 1;
    const int frow = lane >> 2;
    const int fk = lane & 3;

    float acc[2][4][4];
#pragma unroll
    for (int i = 0; i < 2; i++)
#pragma unroll
        for (int j = 0; j < 4; j++)
#pragma unroll
            for (int e = 0; e < 4; e++) acc[i][j][e] = 0.0f;

    const int lm = tid >> 2;
    const int lq = tid & 3;

    float4 pre[2];
    auto ldA = [&](int k0) {
#pragma unroll
        for (int it = 0; it < 2; it++) {
            int kq = lq * 2 + it;
            pre[it] = *(const float4*)(A + (size_t)(bm + lm) * K + k0 + kq * 4);
        }
    };
    auto stA = [&](int buf) {
#pragma unroll
        for (int it = 0; it < 2; it++) {
            int kq = lq * 2 + it;
            uint2 u = make_uint2(pack_h2(pre[it].x, pre[it].y),
                                 pack_h2(pre[it].z, pre[it].w));
            *(uint2*)&As[buf][lm][kq * 2] = u;
        }
    };

    ldA(0);
    stA(0);
    int buf = 0;

    for (int k0 = 0; k0 < K; k0 += 32) {
        __syncthreads();
        bool next = (k0 + 32 < K);
        if (next) ldA(k0 + 32);

#pragma unroll
        for (int sub = 0; sub < 2; sub++) {
            const int k16g = (k0 >> 4) + sub;
            uint32_t b0[4], b1[4];
#pragma unroll
            for (int j = 0; j < 4; j++) {
                size_t nt = (size_t)(bnt + wn * 4 + j);
                const uint2 v = __ldg((const uint2*)(Wf + ((nt * 32 + k16g) * 32 + lane) * 2));
                b0[j] = v.x; b1[j] = v.y;
            }
            uint32_t a[2][4];
#pragma unroll
            for (int i = 0; i < 2; i++) {
                int r0 = wm * 32 + i * 16 + frow;
                a[i][0] = As[buf][r0][sub * 8 + fk];
                a[i][1] = As[buf][r0 + 8][sub * 8 + fk];
                a[i][2] = As[buf][r0][sub * 8 + 4 + fk];
                a[i][3] = As[buf][r0 + 8][sub * 8 + 4 + fk];
            }
#pragma unroll
            for (int i = 0; i < 2; i++)
#pragma unroll
                for (int j = 0; j < 4; j++)
                    MMA_F16(acc[i][j], a[i][0], a[i][1], a[i][2], a[i][3],
                            b0[j], b1[j]);
        }
        if (next) stA(buf ^ 1);
        buf ^= 1;
    }

#pragma unroll
    for (int i = 0; i < 2; i++) {
        int mrow = bm + wm * 32 + i * 16 + frow;
#pragma unroll
        for (int j = 0; j < 4; j++) {
            int ncol = (bnt + wn * 4 + j) * 8 + fk * 2;
            float c0 = bias[ncol], c1 = bias[ncol + 1];
            *(float2*)(C + (size_t)mrow * N + ncol) =
                make_float2(acc[i][j][0] + c0, acc[i][j][1] + c1);
            *(float2*)(C + (size_t)(mrow + 8) * N + ncol) =
                make_float2(acc[i][j][2] + c0, acc[i][j][3] + c1);
        }
    }
}

// ---------------------------------------------------------------------------
// Gen-based barrier (used once at kernel end for counter reset)
// ---------------------------------------------------------------------------
__device__ __forceinline__ void group_barrier(int grp, unsigned nb)
{
    __syncthreads();
    if (threadIdx.x == 0) {
        unsigned gen0 = *(volatile unsigned*)&g_bars[grp].gen;
        unsigned prev = atom_add_rel_gpu(&g_bars[grp].arrive);
        if (prev == nb - 1) {
            *(volatile unsigned*)&g_bars[grp].arrive = 0;
            atom_add_rel_gpu(&g_bars[grp].gen);
        } else {
            while (ld_acq_gpu(&g_bars[grp].gen) == gen0) { }
        }
    }
    __syncthreads();
}

// ---------------------------------------------------------------------------
// Warp-specialized fused 2-layer kernel: warps 0-3 = layer-1 pipeline,
// warps 4-7 = layer-2 pipeline. Coupling only via fp16 mirrors + counters.
// Each pipeline: 4 warps, k-slice 128/warp, named barrier, 4-way reduce.
// 128 CTAs = 32 j-tiles x 4 b-groups, 256 threads.
// ---------------------------------------------------------------------------
#define HSH_PITCH 520
#define PS_PITCH 50
#define W2_ENTRIES (6 * 32 * 32)
#define PS4_BYTES (4 * 16 * PS_PITCH * 4)     // 12800
#define SM_W2I 0
#define SM_W2H (W2_ENTRIES * 8)
#define SM_PSA (2 * W2_ENTRIES * 8)
#define SM_PSB (SM_PSA + PS4_BYTES)
#define SM_PSC (SM_PSB + PS4_BYTES)
#define SM_H1  (SM_PSC + PS4_BYTES)
#define SM_H1B (SM_H1 + 16 * HSH_PITCH * 2)
#define SM_H2  (SM_H1B + 16 * HSH_PITCH * 2)
#define FUSED_SMEM_BYTES (SM_H2 + 16 * HSH_PITCH * 2)   // 186624 B

__global__ __launch_bounds__(256, 1) void gru_fused2(
    const float* __restrict__ gx1_all,  // (T, B, 3H) layer-1 input gates
    const float* __restrict__ h0,       // (L, B, H)
    const float* __restrict__ Whh1,     // (3H, H)
    const float* __restrict__ bhh1,     // (3H)
    const float* __restrict__ Wih2,     // (3H, H)
    const float* __restrict__ bih2,     // (3H)
    const float* __restrict__ Whh2,     // (3H, H)
    const float* __restrict__ bhh2,     // (3H)
    float* __restrict__ out)            // (T, B, H) layer-2 output
{
    extern __shared__ char smc[];
    uint2*  W2i  = (uint2*)(smc + SM_W2I);
    uint2*  W2h  = (uint2*)(smc + SM_W2H);
    float*  Ps_a = (float*)(smc + SM_PSA);
    float*  Ps_b = (float*)(smc + SM_PSB);
    float*  Ps_c = (float*)(smc + SM_PSC);
    __half* h1_s  = (__half*)(smc + SM_H1);    // l1 group's h1[t-1]
    __half* h1b_s = (__half*)(smc + SM_H1B);   // l2 group's h1[s]
    __half* h2_s  = (__half*)(smc + SM_H2);    // l2 group's h2[s-1]

    const int jt = blockIdx.x & 31;
    const int bt = blockIdx.x >> 5;
    const int j0 = jt * 16;
    const int b0 = bt * 16;
    const int tid = threadIdx.x;
    const int w = tid >> 5;
    const int lane = tid & 31;
    const int my_oct = jt >> 2;

    const float* h0_l1 = h0;
    const float* h0_l2 = h0 + (size_t)BATCH * HID;

    // per-128-thread-group mappings
    const int wg_tid = tid & 127;
    const int gb = wg_tid >> 3;          // batch row 0..15
    const int gjp = wg_tid & 7;          // column pair 0..7
    const int bg_g = b0 + gb;
    const int jg0 = j0 + 2 * gjp;        // first of two output columns
    const int frow = lane >> 2;
    const int fk = lane & 3;
    const int pm = lane >> 2;
    const int pnc = 2 * (lane & 3);

    // ---- W2 fragments to SMEM (all 256 threads help)
    for (int i = tid; i < W2_ENTRIES; i += 256) {
        int lane_ = i & 31;
        int k16_ = (i >> 5) & 31;
        int tl_ = i >> 10;
        int g = tl_ >> 1;
        int col = j0 + (tl_ & 1) * 8 + (lane_ >> 2);
        int k = k16_ * 16 + (lane_ & 3) * 2;
        const float* wi = Wih2 + (size_t)(g * HID + col) * HID;
        const float* wh = Whh2 + (size_t)(g * HID + col) * HID;
        W2i[i] = make_uint2(pack_h2(wi[k], wi[k + 1]), pack_h2(wi[k + 8], wi[k + 9]));
        W2h[i] = make_uint2(pack_h2(wh[k], wh[k + 1]), pack_h2(wh[k + 8], wh[k + 9]));
    }
    __syncthreads();   // once, before divergence

    if (w < 4) {
        // ================= LAYER-1 PIPELINE (warps 0-3) =================
        // warp w owns k16 steps [w*8, w*8+8)  (k in [w*128, w*128+128))
        uint32_t wb0[6][8], wb1[6][8];
        {
            const int colq = lane >> 2;
            const int kq2 = (lane & 3) * 2;
#pragma unroll
            for (int tl = 0; tl < 6; tl++) {
                int g = tl >> 1;
                int col = j0 + (tl & 1) * 8 + colq;
                const float* wrow = Whh1 + (size_t)(g * HID + col) * HID;
#pragma unroll
                for (int kk = 0; kk < 8; kk++) {
                    int ks = (w * 8 + kk) * 16 + kq2;
                    wb0[tl][kk] = pack_h2(wrow[ks], wrow[ks + 1]);
                    wb1[tl][kk] = pack_h2(wrow[ks + 8], wrow[ks + 9]);
                }
            }
        }
        float b1r0 = bhh1[jg0],          b1r1 = bhh1[jg0 + 1];
        float b1z0 = bhh1[HID + jg0],    b1z1 = bhh1[HID + jg0 + 1];
        float b1n0 = bhh1[2*HID + jg0],  b1n1 = bhh1[2*HID + jg0 + 1];

        float2 hpv = *(const float2*)(h0_l1 + (size_t)bg_g * HID + jg0);
        const float* gxp = gx1_all + (size_t)bg_g * GATES;
        float2 xr = *(const float2*)(gxp + jg0);
        float2 xz = *(const float2*)(gxp + HID + jg0);
        float2 xn = *(const float2*)(gxp + 2*HID + jg0);

        for (int t = 0; t < T_STEPS; t++) {
            // stage h1[t-1] slice (k in [w*128, w*128+128))
            if (t == 0) {
#pragma unroll
                for (int it = 0; it < 16; it++) {
                    int f = it * 32 + lane;       // 0..511
                    int rr = f >> 5;              // row 0..15
                    int c4 = f & 31;              // float4 within 128 floats
                    float4 v = *((const float4*)(h0_l1 + (size_t)(b0 + rr) * HID + w * 128) + c4);
                    uint2 u = make_uint2(pack_h2(v.x, v.y), pack_h2(v.z, v.w));
                    *(uint2*)&h1_s[rr * HSH_PITCH + w * 128 + c4 * 4] = u;
                }
                __syncwarp();
            } else {
                unsigned tgt = 4u * (unsigned)t;
                unsigned* c0 = &g_cntL[0][bt][2 * w].v;
                unsigned* c1 = &g_cntL[0][bt][2 * w + 1].v;
                while (ld_acq_gpu(c0) < tgt) { }
                while (ld_acq_gpu(c1) < tgt) { }
                const __half* mir = &g_hmir1[(t - 1) & 1][b0][0];
#pragma unroll
                for (int it = 0; it < 8; it++) {
                    int f = it * 32 + lane;       // 0..255
                    int rr = f >> 4;              // row 0..15
                    int c  = f & 15;              // 16B chunk within 256B
                    uint32_t dst = (uint32_t)__cvta_generic_to_shared(
                        &h1_s[rr * HSH_PITCH + w * 128 + c * 8]);
                    cp_async16(dst, mir + (size_t)rr * HID + w * 128 + c * 8);
                }
                asm volatile("cp.async.commit_group;");
                asm volatile("cp.async.wait_group 0;");
                __syncwarp();
            }

            // l1-rec MMAs: 8 k16 x 6 tiles
            float acc[6][4];
#pragma unroll
            for (int tl = 0; tl < 6; tl++) {
                acc[tl][0] = 0.f; acc[tl][1] = 0.f; acc[tl][2] = 0.f; acc[tl][3] = 0.f;
            }
#pragma unroll
            for (int kk = 0; kk < 8; kk++) {
                int kbase = (w * 8 + kk) * 16;
                uint32_t a0 = *(const uint32_t*)&h1_s[frow * HSH_PITCH + kbase + fk * 2];
                uint32_t a1 = *(const uint32_t*)&h1_s[(frow + 8) * HSH_PITCH + kbase + fk * 2];
                uint32_t a2 = *(const uint32_t*)&h1_s[frow * HSH_PITCH + kbase + 8 + fk * 2];
                uint32_t a3 = *(const uint32_t*)&h1_s[(frow + 8) * HSH_PITCH + kbase + 8 + fk * 2];
#pragma unroll
                for (int tl = 0; tl < 6; tl++)
                    MMA_F16(acc[tl], a0, a1, a2, a3, wb0[tl][kk], wb1[tl][kk]);
            }
#pragma unroll
            for (int tl = 0; tl < 6; tl++) {
                *(float2*)&Ps_a[(w * 16 + pm) * PS_PITCH + tl * 8 + pnc] =
                    make_float2(acc[tl][0], acc[tl][1]);
                *(float2*)&Ps_a[(w * 16 + pm + 8) * PS_PITCH + tl * 8 + pnc] =
                    make_float2(acc[tl][2], acc[tl][3]);
            }
            BARX(1);

            // reduce 4 partials (2 outputs per thread) + gating
            float hr0 = 0.f, hr1 = 0.f, hz0 = 0.f, hz1 = 0.f, hn0 = 0.f, hn1 = 0.f;
#pragma unroll
            for (int ww = 0; ww < 4; ww++) {
                const float* p = &Ps_a[(ww * 16 + gb) * PS_PITCH];
                float2 vr = *(const float2*)&p[2 * gjp];
                float2 vz = *(const float2*)&p[16 + 2 * gjp];
                float2 vn = *(const float2*)&p[32 + 2 * gjp];
                hr0 += vr.x; hr1 += vr.y;
                hz0 += vz.x; hz1 += vz.y;
                hn0 += vn.x; hn1 += vn.y;
            }
            float r0 = 1.0f / (1.0f + __expf(-(xr.x + hr0 + b1r0)));
            float r1 = 1.0f / (1.0f + __expf(-(xr.y + hr1 + b1r1)));
            float z0 = 1.0f / (1.0f + __expf(-(xz.x + hz0 + b1z0)));
            float z1 = 1.0f / (1.0f + __expf(-(xz.y + hz1 + b1z1)));
            float n0 = tanhf(xn.x + r0 * (hn0 + b1n0));
            float n1 = tanhf(xn.y + r1 * (hn1 + b1n1));
            float h1x = (1.0f - z0) * n0 + z0 * hpv.x;
            float h1y = (1.0f - z1) * n1 + z1 * hpv.y;
            hpv.x = h1x; hpv.y = h1y;

            // throttle: before overwriting mirror1[t&1], ensure all l2 CTAs
            // finished step t-2 (all 8 cntL[1] >= 4(t-1)); lanes poll 8 ctrs
            if (t >= 2) {
                unsigned tgt2 = 4u * (unsigned)(t - 1);
                unsigned* cc = &g_cntL[1][bt][lane & 7].v;
                while (ld_acq_gpu(cc) < tgt2) { }
            }
            *(uint32_t*)&g_hmir1[t & 1][bg_g][jg0] = pack_h2(h1x, h1y);
            BARX(1);   // all 4 warps' mirror writes precede the release
            if (wg_tid == 0)
                red_add_rel_gpu(&g_cntL[0][bt][my_oct].v);

            // prefetch next gx1
            int tn = (t + 1 < T_STEPS) ? t + 1 : t;
            const float* gxn = gx1_all + (size_t)tn * BATCH * GATES + (size_t)bg_g * GATES;
            xr = *(const float2*)(gxn + jg0);
            xz = *(const float2*)(gxn + HID + jg0);
            xn = *(const float2*)(gxn + 2*HID + jg0);
        }
    } else {
        // ================= LAYER-2 PIPELINE (warps 4-7) =================
        const int wg = w - 4;            // 0..3, k16 steps [wg*8, wg*8+8)
        float i2r0 = bih2[jg0],          i2r1 = bih2[jg0 + 1];
        float i2z0 = bih2[HID + jg0],    i2z1 = bih2[HID + jg0 + 1];
        float i2n0 = bih2[2*HID + jg0],  i2n1 = bih2[2*HID + jg0 + 1];
        float h2r0 = bhh2[jg0],          h2r1 = bhh2[jg0 + 1];
        float h2z0 = bhh2[HID + jg0],    h2z1 = bhh2[HID + jg0 + 1];
        float h2n0 = bhh2[2*HID + jg0],  h2n1 = bhh2[2*HID + jg0 + 1];

        float2 hpv = *(const float2*)(h0_l2 + (size_t)bg_g * HID + jg0);

        for (int s = 0; s < T_STEPS; s++) {
            // stage h1[s] slice from mirror1 (wait l1 published step s)
            {
                unsigned tgt = 4u * (unsigned)(s + 1);
                unsigned* c0 = &g_cntL[0][bt][2 * wg].v;
                unsigned* c1 = &g_cntL[0][bt][2 * wg + 1].v;
                while (ld_acq_gpu(c0) < tgt) { }
                while (ld_acq_gpu(c1) < tgt) { }
                const __half* mir = &g_hmir1[s & 1][b0][0];
#pragma unroll
                for (int it = 0; it < 8; it++) {
                    int f = it * 32 + lane;
                    int rr = f >> 4;
                    int c  = f & 15;
                    uint32_t dst = (uint32_t)__cvta_generic_to_shared(
                        &h1b_s[rr * HSH_PITCH + wg * 128 + c * 8]);
                    cp_async16(dst, mir + (size_t)rr * HID + wg * 128 + c * 8);
                }
                asm volatile("cp.async.commit_group;");
            }
            // stage h2[s-1] slice
            if (s == 0) {
#pragma unroll
                for (int it = 0; it < 16; it++) {
                    int f = it * 32 + lane;
                    int rr = f >> 5;
                    int c4 = f & 31;
                    float4 v = *((const float4*)(h0_l2 + (size_t)(b0 + rr) * HID + wg * 128) + c4);
                    uint2 u = make_uint2(pack_h2(v.x, v.y), pack_h2(v.z, v.w));
                    *(uint2*)&h2_s[rr * HSH_PITCH + wg * 128 + c4 * 4] = u;
                }
            } else {
                unsigned tgt = 4u * (unsigned)s;
                unsigned* c0 = &g_cntL[1][bt][2 * wg].v;
                unsigned* c1 = &g_cntL[1][bt][2 * wg + 1].v;
                while (ld_acq_gpu(c0) < tgt) { }
                while (ld_acq_gpu(c1) < tgt) { }
                const __half* mir = &g_hmir2[(s - 1) & 1][b0][0];
#pragma unroll
                for (int it = 0; it < 8; it++) {
                    int f = it * 32 + lane;
                    int rr = f >> 4;
                    int c  = f & 15;
                    uint32_t dst = (uint32_t)__cvta_generic_to_shared(
                        &h2_s[rr * HSH_PITCH + wg * 128 + c * 8]);
                    cp_async16(dst, mir + (size_t)rr * HID + wg * 128 + c * 8);
                }
                asm volatile("cp.async.commit_group;");
            }
            asm volatile("cp.async.wait_all;");
            __syncwarp();

            // l2-inp MMAs (h1b) -> Ps_c ; l2-rec MMAs (h2) -> Ps_b
            float acc[6][4];
#pragma unroll
            for (int tl = 0; tl < 6; tl++) {
                acc[tl][0] = 0.f; acc[tl][1] = 0.f; acc[tl][2] = 0.f; acc[tl][3] = 0.f;
            }
#pragma unroll
            for (int kk = 0; kk < 8; kk++) {
                int k16g = wg * 8 + kk;
                int kbase = k16g * 16;
                uint32_t a0 = *(const uint32_t*)&h1b_s[frow * HSH_PITCH + kbase + fk * 2];
                uint32_t a1 = *(const uint32_t*)&h1b_s[(frow + 8) * HSH_PITCH + kbase + fk * 2];
                uint32_t a2 = *(const uint32_t*)&h1b_s[frow * HSH_PITCH + kbase + 8 + fk * 2];
                uint32_t a3 = *(const uint32_t*)&h1b_s[(frow + 8) * HSH_PITCH + kbase + 8 + fk * 2];
#pragma unroll
                for (int tl = 0; tl < 6; tl++) {
                    uint2 bv = W2i[(tl * 32 + k16g) * 32 + lane];
                    MMA_F16(acc[tl], a0, a1, a2, a3, bv.x, bv.y);
                }
            }
#pragma unroll
            for (int tl = 0; tl < 6; tl++) {
                *(float2*)&Ps_c[(wg * 16 + pm) * PS_PITCH + tl * 8 + pnc] =
                    make_float2(acc[tl][0], acc[tl][1]);
                *(float2*)&Ps_c[(wg * 16 + pm + 8) * PS_PITCH + tl * 8 + pnc] =
                    make_float2(acc[tl][2], acc[tl][3]);
            }
#pragma unroll
            for (int tl = 0; tl < 6; tl++) {
                acc[tl][0] = 0.f; acc[tl][1] = 0.f; acc[tl][2] = 0.f; acc[tl][3] = 0.f;
            }
#pragma unroll
            for (int kk = 0; kk < 8; kk++) {
                int k16g = wg * 8 + kk;
                int kbase = k16g * 16;
                uint32_t a0 = *(const uint32_t*)&h2_s[frow * HSH_PITCH + kbase + fk * 2];
                uint32_t a1 = *(const uint32_t*)&h2_s[(frow + 8) * HSH_PITCH + kbase + fk * 2];
                uint32_t a2 = *(const uint32_t*)&h2_s[frow * HSH_PITCH + kbase + 8 + fk * 2];
                uint32_t a3 = *(const uint32_t*)&h2_s[(frow + 8) * HSH_PITCH + kbase + 8 + fk * 2];
#pragma unroll
                for (int tl = 0; tl < 6; tl++) {
                    uint2 bv = W2h[(tl * 32 + k16g) * 32 + lane];
                    MMA_F16(acc[tl], a0, a1, a2, a3, bv.x, bv.y);
                }
            }
#pragma unroll
            for (int tl = 0; tl < 6; tl++) {
                *(float2*)&Ps_b[(wg * 16 + pm) * PS_PITCH + tl * 8 + pnc] =
                    make_float2(acc[tl][0], acc[tl][1]);
                *(float2*)&Ps_b[(wg * 16 + pm + 8) * PS_PITCH + tl * 8 + pnc] =
                    make_float2(acc[tl][2], acc[tl][3]);
            }
            BARX(2);

            // reduce + gating (2 outputs per thread)
            float xr0 = 0.f, xr1 = 0.f, xz0 = 0.f, xz1 = 0.f, xn0 = 0.f, xn1 = 0.f;
            float hr0 = 0.f, hr1 = 0.f, hz0 = 0.f, hz1 = 0.f, hn0 = 0.f, hn1 = 0.f;
#pragma unroll
            for (int ww = 0; ww < 4; ww++) {
                const float* pa = &Ps_c[(ww * 16 + gb) * PS_PITCH];
                const float* pb = &Ps_b[(ww * 16 + gb) * PS_PITCH];
                float2 v;
                v = *(const float2*)&pa[2 * gjp];       xr0 += v.x; xr1 += v.y;
                v = *(const float2*)&pa[16 + 2 * gjp];  xz0 += v.x; xz1 += v.y;
                v = *(const float2*)&pa[32 + 2 * gjp];  xn0 += v.x; xn1 += v.y;
                v = *(const float2*)&pb[2 * gjp];       hr0 += v.x; hr1 += v.y;
                v = *(const float2*)&pb[16 + 2 * gjp];  hz0 += v.x; hz1 += v.y;
                v = *(const float2*)&pb[32 + 2 * gjp];  hn0 += v.x; hn1 += v.y;
            }
            float r0 = 1.0f / (1.0f + __expf(-(xr0 + i2r0 + hr0 + h2r0)));
            float r1 = 1.0f / (1.0f + __expf(-(xr1 + i2r1 + hr1 + h2r1)));
            float z0 = 1.0f / (1.0f + __expf(-(xz0 + i2z0 + hz0 + h2z0)));
            float z1 = 1.0f / (1.0f + __expf(-(xz1 + i2z1 + hz1 + h2z1)));
            float n0 = tanhf(xn0 + i2n0 + r0 * (hn0 + h2n0));
            float n1 = tanhf(xn1 + i2n1 + r1 * (hn1 + h2n1));
            float h2x = (1.0f - z0) * n0 + z0 * hpv.x;
            float h2y = (1.0f - z1) * n1 + z1 * hpv.y;
            hpv.x = h2x; hpv.y = h2y;

            *(uint32_t*)&g_hmir2[s & 1][bg_g][jg0] = pack_h2(h2x, h2y);
            *(float2*)(out + (size_t)s * BATCH * HID + (size_t)bg_g * HID + jg0) =
                make_float2(h2x, h2y);
            BARX(2);   // all 4 warps' mirror writes precede the release
            if (wg_tid == 0)
                red_add_rel_gpu(&g_cntL[1][bt][my_oct].v);
        }
    }

    // end: fence the group, then reset this group's counters (both layers)
    group_barrier(bt, 32);
    if (jt == 0 && tid < 8) {
        *(volatile unsigned*)&g_cntL[0][bt][tid].v = 0;
        *(volatile unsigned*)&g_cntL[1][bt][tid].v = 0;
    }
}

// ---------------------------------------------------------------------------
extern "C" void kernel_launch(void* const* d_in, const int* in_sizes, int n_in,
                              void* d_out, int out_size)
{
    const float* x    = (const float*)d_in[0];
    const float* h0   = (const float*)d_in[1];
    const float* w_ih = (const float*)d_in[2];
    const float* w_hh = (const float*)d_in[3];
    const float* b_ih = (const float*)d_in[4];
    const float* b_hh = (const float*)d_in[5];
    float* out_final  = (float*)d_out;

    float* gates; uint32_t* wfrag;
    cudaGetSymbolAddress((void**)&gates, g_gates);
    cudaGetSymbolAddress((void**)&wfrag, g_wfrag);

    static int smem_configured = 0;
    if (!smem_configured) {
        cudaFuncSetAttribute(gru_fused2,
                             cudaFuncAttributeMaxDynamicSharedMemorySize, FUSED_SMEM_BYTES);
        smem_configured = 1;
    }

    const int M = T_STEPS * BATCH;
    const int K = HID;

    // layer-1 input GEMM (parallel, off the serial path)
    conv_wfrag_h<<<1536, 256>>>(w_ih, wfrag);
    dim3 ggrid(GATES / 128, M / 64);
    gemm_f16<<<ggrid, 256>>>(x, wfrag, b_ih, gates, M, GATES, K);

    // warp-specialized dual-pipeline recurrence
    gru_fused2<<<128, 256, FUSED_SMEM_BYTES>>>(
        gates, h0,
        w_hh, b_hh,                                   // layer-1 recurrent
        w_ih + (size_t)GATES * HID, b_ih + GATES,     // layer-2 input
        w_hh + (size_t)GATES * HID, b_hh + GATES,     // layer-2 recurrent
        out_final);
}